// round 9
// baseline (speedup 1.0000x reference)
#include <cuda_runtime.h>
#include <cuda_bf16.h>
#include <mma.h>
#include <cstdint>

using namespace nvcuda;

#define NB 64
#define NN 1024
#define ND 128
#define THRESH 0.15f      // 0.5 - MARGIN(0.35)
#define TM 128            // A tile rows (pos)
#define TN 64             // streamed B tile rows (neg)
#define LDSE 136          // smem leading dim in bf16 elems (272B rows)
#define ROWB (LDSE * 2)
#define A_BYTES (TM * ROWB)           // 34816
#define B_BYTES (TN * ROWB)           // 17408
#define SMEM_DYN (A_BYTES + 2 * B_BYTES)  // 69632 -> occ 3
#define GEMM_CTAS (8 * NB)            // 512

// Scratch (device globals; no allocation allowed)
__device__ __nv_bfloat16 g_P[(size_t)NB * NN * ND];
__device__ __nv_bfloat16 g_Q[(size_t)NB * NN * ND];
__device__ unsigned short g_dest[NB * NN];
__device__ int   g_npos[NB];
__device__ int   g_nneg[NB];
__device__ float g_bsum[NB];
__device__ unsigned int g_done;

__device__ __forceinline__ uint32_t smem_u32(const void* p) {
    uint32_t a;
    asm("{ .reg .u64 t; cvta.to.shared.u64 t, %1; cvt.u32.u64 %0, t; }" : "=r"(a) : "l"(p));
    return a;
}
__device__ __forceinline__ void cp16(uint32_t dst, const void* src) {
    asm volatile("cp.async.cg.shared.global [%0], [%1], 16;" :: "r"(dst), "l"(src));
}
#define CP_COMMIT() asm volatile("cp.async.commit_group;" ::: "memory")
#define CP_WAIT(n)  asm volatile("cp.async.wait_group %0;" :: "n"(n) : "memory")

// ---------------------------------------------------------------------------
// Kernel A0: per-batch compaction map via block scan + zero pad rows
// grid = 64, block = 256 (int4 labels, 4 per thread)   [R7-proven]
// ---------------------------------------------------------------------------
__global__ void __launch_bounds__(256)
scan_kernel(const int* __restrict__ labels)
{
    const int b = blockIdx.x;
    const int tid = threadIdx.x;
    const int warp = tid >> 5, lane = tid & 31;

    __shared__ int s_wtot[8];

    int4 l4 = reinterpret_cast<const int4*>(labels + b * NN)[tid];
    int p0 = (l4.x == 1), p1 = (l4.y == 1), p2 = (l4.z == 1), p3 = (l4.w == 1);
    int tsum = p0 + p1 + p2 + p3;

    int incl = tsum;
#pragma unroll
    for (int o = 1; o < 32; o <<= 1) {
        int v = __shfl_up_sync(0xFFFFFFFFu, incl, o);
        if (lane >= o) incl += v;
    }
    if (lane == 31) s_wtot[warp] = incl;
    __syncthreads();
    if (tid < 8) {
        int v = s_wtot[tid];
#pragma unroll
        for (int o = 1; o < 8; o <<= 1) {
            int u = __shfl_up_sync(0x000000FFu, v, o);
            if (lane >= o) v += u;
        }
        s_wtot[tid] = v;
    }
    __syncthreads();

    int run = (warp > 0 ? s_wtot[warp - 1] : 0) + incl - tsum;
    int base4 = tid * 4;
    int pp[4] = {p0, p1, p2, p3};
#pragma unroll
    for (int j = 0; j < 4; j++) {
        int idx = base4 + j;
        int rank = pp[j] ? run : (idx - run);
        g_dest[b * NN + idx] = (unsigned short)(rank | (pp[j] << 15));
        run += pp[j];
    }

    const int npos = s_wtot[7];
    const int nneg = NN - npos;
    if (tid == 0) {
        g_npos[b] = npos; g_nneg[b] = nneg; g_bsum[b] = 0.0f;
        if (b == 0) g_done = 0u;
    }

    // zero-pad P tail to TM=128, Q tail to TN=64 granularity
    const uint4 z4 = make_uint4(0u, 0u, 0u, 0u);
    int pad_pos = min(NN, ((npos + TM - 1) / TM) * TM);
    int pad_neg = min(NN, ((nneg + TN - 1) / TN) * TN);
    int nzp = (pad_pos - npos) * 16;
    for (int i = tid; i < nzp; i += 256) {
        int r = npos + (i >> 4), c = i & 15;
        reinterpret_cast<uint4*>(g_P + ((size_t)b * NN + r) * ND)[c] = z4;
    }
    int nzn = (pad_neg - nneg) * 16;
    for (int i = tid; i < nzn; i += 256) {
        int r = nneg + (i >> 4), c = i & 15;
        reinterpret_cast<uint4*>(g_Q + ((size_t)b * NN + r) * ND)[c] = z4;
    }
}

// ---------------------------------------------------------------------------
// Kernel A1: normalize + compacted scatter. One warp per row.  [R7-proven]
// ---------------------------------------------------------------------------
__global__ void __launch_bounds__(256)
normalize_scatter_kernel(const float* __restrict__ emb)
{
    const int b = blockIdx.y;
    const int wid  = threadIdx.x >> 5;
    const int lane = threadIdx.x & 31;
    const int r = blockIdx.x * 8 + wid;

    const float* src = emb + ((size_t)b * NN + r) * ND;
    float v[4];
    float ss = 0.0f;
#pragma unroll
    for (int i = 0; i < 4; i++) { v[i] = src[lane + 32 * i]; ss += v[i] * v[i]; }
#pragma unroll
    for (int o = 16; o > 0; o >>= 1) ss += __shfl_xor_sync(0xFFFFFFFFu, ss, o);
    float inv = 1.0f / fmaxf(sqrtf(ss), 1e-12f);

    unsigned short d = g_dest[b * NN + r];
    int rank  = d & 0x7FFF;
    int ispos = d >> 15;
    __nv_bfloat16* dst = (ispos ? g_P : g_Q) + ((size_t)b * NN + rank) * ND;
#pragma unroll
    for (int i = 0; i < 4; i++) dst[lane + 32 * i] = __float2bfloat16(v[i] * inv);
}

// ---------------------------------------------------------------------------
// Kernel B: A-resident streaming GEMM, occ 3. CTA = (ti, b): A 128 rows once,
// stream 64-row B tiles double-buffered. 256 thr, warp tile 32x32 (4x2 warps).
// ---------------------------------------------------------------------------
__global__ void __launch_bounds__(256, 3)
hinge_gemm_kernel(float* __restrict__ out)
{
    extern __shared__ __align__(16) char smem[];
    const uint32_t smem_base = smem_u32(smem);
    const int tid  = threadIdx.x;
    const int warp = tid >> 5;
    const int lane = tid & 31;

    const int ti = blockIdx.x;
    const int b  = blockIdx.y;
    const int npos = g_npos[b];
    const int nneg = g_nneg[b];
    const int njt  = (nneg + TN - 1) / TN;
    const bool active = (ti * TM < npos) && (njt > 0);

    if (active) {
        const char* P  = (const char*)(g_P + ((size_t)b * NN + ti * TM) * ND);
        const char* Qb = (const char*)(g_Q + (size_t)b * NN * ND);

        // load A (8 chunks/thread) + first B (4 chunks/thread), one group
        for (int t = tid; t < TM * 16; t += 256) {
            int r = t >> 4, c = t & 15;
            cp16(smem_base + r * ROWB + c * 16, P + (size_t)r * ND * 2 + c * 16);
        }
        for (int t = tid; t < TN * 16; t += 256) {
            int r = t >> 4, c = t & 15;
            cp16(smem_base + A_BYTES + r * ROWB + c * 16, Qb + (size_t)r * ND * 2 + c * 16);
        }
        CP_COMMIT();

        const __nv_bfloat16* sA = (const __nv_bfloat16*)(smem);
        const int wrow = warp & 3;    // 0..3 -> A rows wrow*32
        const int wcol = warp >> 2;   // 0..1 -> B rows wcol*32

        float s = 0.0f;

        for (int tj = 0; tj < njt; tj++) {
            const int cbuf = tj & 1;
            if (tj + 1 < njt) {
                const char* Qn = Qb + (size_t)(tj + 1) * TN * ND * 2;
                uint32_t sBn = smem_base + A_BYTES + B_BYTES * ((tj + 1) & 1);
                for (int t = tid; t < TN * 16; t += 256) {
                    int r = t >> 4, c = t & 15;
                    cp16(sBn + r * ROWB + c * 16, Qn + (size_t)r * ND * 2 + c * 16);
                }
                CP_COMMIT();
                CP_WAIT(1);
            } else {
                CP_WAIT(0);
            }
            __syncthreads();

            const __nv_bfloat16* sB =
                (const __nv_bfloat16*)(smem + A_BYTES + B_BYTES * cbuf);

            wmma::fragment<wmma::accumulator, 16, 16, 16, float> acc[2][2];
#pragma unroll
            for (int i = 0; i < 2; i++)
#pragma unroll
                for (int j = 0; j < 2; j++) wmma::fill_fragment(acc[i][j], 0.0f);

#pragma unroll
            for (int k = 0; k < ND; k += 16) {
                wmma::fragment<wmma::matrix_a, 16, 16, 16, __nv_bfloat16, wmma::row_major> a[2];
                wmma::fragment<wmma::matrix_b, 16, 16, 16, __nv_bfloat16, wmma::col_major> bb[2];
#pragma unroll
                for (int i = 0; i < 2; i++)
                    wmma::load_matrix_sync(a[i], sA + (wrow * 32 + i * 16) * LDSE + k, LDSE);
#pragma unroll
                for (int j = 0; j < 2; j++)
                    wmma::load_matrix_sync(bb[j], sB + (wcol * 32 + j * 16) * LDSE + k, LDSE);
#pragma unroll
                for (int i = 0; i < 2; i++)
#pragma unroll
                    for (int j = 0; j < 2; j++)
                        wmma::mma_sync(acc[i][j], a[i], bb[j], acc[i][j]);
            }

#pragma unroll
            for (int i = 0; i < 2; i++)
#pragma unroll
                for (int j = 0; j < 2; j++)
#pragma unroll
                    for (int e = 0; e < acc[i][j].num_elements; e++)
                        s += fmaxf(acc[i][j].x[e] - THRESH, 0.0f);

            __syncthreads();   // compute done before buffer cbuf is refilled
        }

        // one reduce + one atomic per CTA
#pragma unroll
        for (int o = 16; o > 0; o >>= 1) s += __shfl_xor_sync(0xFFFFFFFFu, s, o);
        __shared__ float s_w[8];
        if (lane == 0) s_w[warp] = s;
        __syncthreads();
        if (tid == 0) {
            float ts = 0.0f;
#pragma unroll
            for (int i = 0; i < 8; i++) ts += s_w[i];
            atomicAdd(&g_bsum[b], ts);
        }
    }

    // completion ticket; last CTA computes the final scalar
    __shared__ unsigned int s_rank;
    if (tid == 0) {
        __threadfence();
        s_rank = atomicAdd(&g_done, 1u);
    }
    __syncthreads();
    if (s_rank == GEMM_CTAS - 1 && tid == 0) {
        __threadfence();
        float L = 0.0f, C = 0.0f;
        for (int i = 0; i < NB; i++) {
            int np = g_npos[i], nn = g_nneg[i];
            if (np > 0 && nn > 0) {
                L += g_bsum[i] / (float)nn;
                C += (float)np;
            }
        }
        out[0] = L / fmaxf(C, 1.0f);
    }
}

// ---------------------------------------------------------------------------
extern "C" void kernel_launch(void* const* d_in, const int* in_sizes, int n_in,
                              void* d_out, int out_size)
{
    const float* emb    = (const float*)d_in[0];
    const int*   labels = (const int*)d_in[1];
    float*       out    = (float*)d_out;

    cudaFuncSetAttribute(hinge_gemm_kernel,
                         cudaFuncAttributeMaxDynamicSharedMemorySize, SMEM_DYN);

    scan_kernel<<<NB, 256>>>(labels);

    dim3 gridA(NN / 8, NB);
    normalize_scatter_kernel<<<gridA, 256>>>(emb);

    dim3 gridB(8, NB);   // (ti, b) = 512 CTAs
    hinge_gemm_kernel<<<gridB, 256, SMEM_DYN>>>(out);
}